// round 14
// baseline (speedup 1.0000x reference)
#include <cuda_runtime.h>
#include <cuda_bf16.h>
#include <cstdint>

// Embedding gather: out[row, :] = w[x[row], :]
// x: [16384] int32, w: [50257, 1024] fp32, out: [16384, 1024] fp32
//
// FINAL (champion config, R8, 16.86 us). Measured findings over 13 rounds:
//   - hot gathered w rows (~14K unique = ~57 MB) kept L2-resident via
//     ld.global.nc + L2::evict_last              -> ~0.3 us win
//   - out (64 MB, zero reuse) via st.global.cs streaming stores so the write
//     stream never occupies L2                    -> ~5 us win
//   - ANY L2 retention for writes (full/half/fractional-25%) thrashes the
//     read set and loses 1.5-4.5 us (falsified 3x)
//   - MLP>4, 256-bit ops, persistent grids: neutral or worse
// Steady state = L2-hit reads + mandatory 64 MB DRAM write-drain (~3.8 TB/s),
// which is the measured memory-system equilibrium for this access pattern.

#define EMB_DIM 1024
#define VEC_PER_ROW (EMB_DIM / 4)   // 256 float4 per row
#define ROWS_PER_BLOCK 4

__device__ __forceinline__ float4 ldg_el(const float4* p, uint64_t pol) {
    float4 v;
    asm volatile("ld.global.nc.L2::cache_hint.v4.f32 {%0,%1,%2,%3}, [%4], %5;"
                 : "=f"(v.x), "=f"(v.y), "=f"(v.z), "=f"(v.w)
                 : "l"(p), "l"(pol));
    return v;
}

__device__ __forceinline__ void stcs_f4(float4* p, float4 v) {
    asm volatile("st.global.cs.v4.f32 [%0], {%1,%2,%3,%4};"
                 :: "l"(p), "f"(v.x), "f"(v.y), "f"(v.z), "f"(v.w) : "memory");
}

__global__ void __launch_bounds__(256, 8) embedding_gather_kernel(
    const int* __restrict__ x,
    const float4* __restrict__ w,
    float4* __restrict__ out,
    int n_rows)
{
    uint64_t pol;
    asm("createpolicy.fractional.L2::evict_last.b64 %0, 1.0;" : "=l"(pol));

    int row0 = blockIdx.x * ROWS_PER_BLOCK;
    int c = threadIdx.x;                       // column slot 0..255

    // Uniform index load: 4 ints as one int4 (16B-aligned since row0%4==0)
    int4 ia = __ldg((const int4*)(x + row0));

    const float4* base = w + c;

    // Front-batched independent gathers: MLP = 4, pinned in L2 (evict_last)
    float4 v0 = ldg_el(base + (size_t)ia.x * VEC_PER_ROW, pol);
    float4 v1 = ldg_el(base + (size_t)ia.y * VEC_PER_ROW, pol);
    float4 v2 = ldg_el(base + (size_t)ia.z * VEC_PER_ROW, pol);
    float4 v3 = ldg_el(base + (size_t)ia.w * VEC_PER_ROW, pol);

    // Streaming stores: keep the write stream OUT of L2
    float4* dst = out + (size_t)row0 * VEC_PER_ROW + c;
    stcs_f4(dst + 0 * VEC_PER_ROW, v0);
    stcs_f4(dst + 1 * VEC_PER_ROW, v1);
    stcs_f4(dst + 2 * VEC_PER_ROW, v2);
    stcs_f4(dst + 3 * VEC_PER_ROW, v3);
}

extern "C" void kernel_launch(void* const* d_in, const int* in_sizes, int n_in,
                              void* d_out, int out_size) {
    const int*    x = (const int*)d_in[0];          // [16384] indices
    const float4* w = (const float4*)d_in[1];       // [50257*1024] fp32 as float4
    float4*       o = (float4*)d_out;

    int n_rows = in_sizes[0];                       // 16384
    int n_blocks = n_rows / ROWS_PER_BLOCK;         // 4096
    embedding_gather_kernel<<<n_blocks, 256>>>(x, w, o, n_rows);
}

// round 15
// speedup vs baseline: 1.4721x; 1.4721x over previous
#include <cuda_runtime.h>
#include <cuda_bf16.h>
#include <cstdint>

// Embedding gather: out[row, :] = w[x[row], :]
// x: [16384] int32, w: [50257, 1024] fp32, out: [16384, 1024] fp32
//
// CHAMPION CONFIG (R8: 16.86 us; R14 rerun of identical source: 25.34 us with
// a shifted ncu profile => chip clock-state variance, not a code effect).
// Resubmitted unchanged as a variance probe per rigor.md.
//
// Robust measured findings (stable across machine states):
//   - out (64 MB, zero reuse) via st.global.cs streaming stores: the ~17 us
//     cluster vs 21-25 us for ANY L2-retentive store policy (falsified 3x).
//   - gathered w rows: ld.global.nc + L2::evict_last (hot ~57 MB L2-resident
//     across graph replays).
//   - MLP=4 front-batched gathers, 4 rows/block, 256 threads, grid 4096.

#define EMB_DIM 1024
#define VEC_PER_ROW (EMB_DIM / 4)   // 256 float4 per row
#define ROWS_PER_BLOCK 4

__device__ __forceinline__ float4 ldg_el(const float4* p, uint64_t pol) {
    float4 v;
    asm volatile("ld.global.nc.L2::cache_hint.v4.f32 {%0,%1,%2,%3}, [%4], %5;"
                 : "=f"(v.x), "=f"(v.y), "=f"(v.z), "=f"(v.w)
                 : "l"(p), "l"(pol));
    return v;
}

__device__ __forceinline__ void stcs_f4(float4* p, float4 v) {
    asm volatile("st.global.cs.v4.f32 [%0], {%1,%2,%3,%4};"
                 :: "l"(p), "f"(v.x), "f"(v.y), "f"(v.z), "f"(v.w) : "memory");
}

__global__ void __launch_bounds__(256, 8) embedding_gather_kernel(
    const int* __restrict__ x,
    const float4* __restrict__ w,
    float4* __restrict__ out,
    int n_rows)
{
    uint64_t pol;
    asm("createpolicy.fractional.L2::evict_last.b64 %0, 1.0;" : "=l"(pol));

    int row0 = blockIdx.x * ROWS_PER_BLOCK;
    int c = threadIdx.x;                       // column slot 0..255

    // Uniform index load: 4 ints as one int4 (16B-aligned since row0%4==0)
    int4 ia = __ldg((const int4*)(x + row0));

    const float4* base = w + c;

    // Front-batched independent gathers: MLP = 4, pinned in L2 (evict_last)
    float4 v0 = ldg_el(base + (size_t)ia.x * VEC_PER_ROW, pol);
    float4 v1 = ldg_el(base + (size_t)ia.y * VEC_PER_ROW, pol);
    float4 v2 = ldg_el(base + (size_t)ia.z * VEC_PER_ROW, pol);
    float4 v3 = ldg_el(base + (size_t)ia.w * VEC_PER_ROW, pol);

    // Streaming stores: keep the write stream OUT of L2
    float4* dst = out + (size_t)row0 * VEC_PER_ROW + c;
    stcs_f4(dst + 0 * VEC_PER_ROW, v0);
    stcs_f4(dst + 1 * VEC_PER_ROW, v1);
    stcs_f4(dst + 2 * VEC_PER_ROW, v2);
    stcs_f4(dst + 3 * VEC_PER_ROW, v3);
}

extern "C" void kernel_launch(void* const* d_in, const int* in_sizes, int n_in,
                              void* d_out, int out_size) {
    const int*    x = (const int*)d_in[0];          // [16384] indices
    const float4* w = (const float4*)d_in[1];       // [50257*1024] fp32 as float4
    float4*       o = (float4*)d_out;

    int n_rows = in_sizes[0];                       // 16384
    int n_blocks = n_rows / ROWS_PER_BLOCK;         // 4096
    embedding_gather_kernel<<<n_blocks, 256>>>(x, w, o, n_rows);
}